// round 16
// baseline (speedup 1.0000x reference)
#include <cuda_runtime.h>
#include <cuda_bf16.h>
#include <cstdint>

// PCEN via exact parallel linear-recurrence scan (constant per-row decay a=1-s).
// R16: R15's dynamic lookahead mailbox (full-iteration prefetch window, 2
// buffers, 3 CTAs/SM) with R13's LSU ordering: wait_group -> pass1 lds128
// (critical path) -> THEN issue next-row cp.async burst. Avoids the LDGSTS
// burst blocking pass1's shared loads in the MIO queue (the R15 regression).

#define TT     8000
#define CHUNK  2000
#define NTH    512
#define GRID_MAX 444            // 3 CTAs/SM * 148 SMs
#define ALPHA_C 0.98f
#define DELTA_C 2.0f
#define EPS_C   1e-6f
#define SQRT_DELTA 1.41421356237f
#define LOG2E 1.44269504089f

// smem floats: buf[2][8000], scr[2][72]
// scr layout: [0..63] warp totals, [64..67] t499 partials, [68] mailbox,
//             [70],[71] prologue row ids (scr0 only)
#define OFF_SCR   (2*TT)
#define SCR_SIZE  72
#define SMEM_FLOATS (2*TT + 2*SCR_SIZE)

__device__ int g_next_row;

__global__ void pcen_init() { g_next_row = 0; }

__device__ __forceinline__ float f_lg2(float x) {
    float r; asm("lg2.approx.f32 %0, %1;" : "=f"(r) : "f"(x)); return r;
}
__device__ __forceinline__ float f_ex2(float x) {
    float r; asm("ex2.approx.f32 %0, %1;" : "=f"(r) : "f"(x)); return r;
}
__device__ __forceinline__ float f_sqrt(float x) {
    float r; asm("sqrt.approx.f32 %0, %1;" : "=f"(r) : "f"(x)); return r;
}
__device__ __forceinline__ float f_rcp(float x) {
    float r; asm("rcp.approx.f32 %0, %1;" : "=f"(r) : "f"(x)); return r;
}
__device__ __forceinline__ void cp16(uint32_t saddr, const float* g) {
    asm volatile("cp.async.cg.shared.global [%0], [%1], 16;"
                 :: "r"(saddr), "l"(g));
}
__device__ __forceinline__ void stg_cs(float* g, float a, float b, float c, float d) {
    asm volatile("st.global.cs.v4.f32 [%0], {%1,%2,%3,%4};"
                 :: "l"(g), "f"(a), "f"(b), "f"(c), "f"(d));
}
__device__ __forceinline__ float4 lds128(uint32_t saddr) {
    float4 v;
    asm volatile("ld.shared.v4.f32 {%0,%1,%2,%3}, [%4];"
                 : "=f"(v.x), "=f"(v.y), "=f"(v.z), "=f"(v.w) : "r"(saddr));
    return v;
}

__global__ __launch_bounds__(NTH, 3)
void pcen_kernel(const float* __restrict__ x,
                 const float* __restrict__ log_s,
                 float* __restrict__ out,
                 int F, int Fmask, int rows)
{
    extern __shared__ float smem[];

    const int t    = threadIdx.x;
    const bool active = (t < CHUNK / 4);       // threads 0..499
    const int lane = t & 31;
    const int wid  = t >> 5;                   // 0..15

    const uint32_t sbase = (uint32_t)__cvta_generic_to_shared(smem);
    const uint32_t sthr  = sbase + 16u * (uint32_t)t;

    // ---- prologue: grab TWO rows ----
    if (t == 0) {
        int r0 = atomicAdd(&g_next_row, 1);
        int r1 = atomicAdd(&g_next_row, 1);
        smem[OFF_SCR + 70] = __int_as_float(r0);
        smem[OFF_SCR + 71] = __int_as_float(r1);
    }
    __syncthreads();
    int row  = __float_as_int(smem[OFF_SCR + 70]);
    int nrow = __float_as_int(smem[OFF_SCR + 71]);
    __syncthreads();   // all reads done before any later scr writes

    float s_cur = 0.0f, s_nx = 0.0f;
    if (row < rows) {
        int f0 = (Fmask >= 0) ? (row & Fmask) : (row % F);
        s_cur = __ldg(log_s + f0);
        if (active) {
            const long long o = (long long)row * TT;
            #pragma unroll
            for (int c = 0; c < 4; c++)
                cp16(sthr + (uint32_t)c * (4u * CHUNK), x + o + c * CHUNK + 4 * t);
        }
    }
    asm volatile("cp.async.commit_group;");
    if (nrow < rows) {
        int f1 = (Fmask >= 0) ? (nrow & Fmask) : (nrow % F);
        s_nx = __ldg(log_s + f1);
    }

    int bufsel = 0, scrsel = 0;
    while (row < rows) {
        // ---- 1. wait for current row's data (older group) ----
        asm volatile("cp.async.wait_group 0;");  // only 1 group can be pending here?
        // NOTE: at this point the only committed-unwaited groups are:
        //   (older) current row's copies, (none newer). nrow's prefetch is
        //   issued BELOW, after pass1's critical-path LDS reads.

        // ---- per-row constants ----
        const float s = f_ex2(LOG2E * s_cur);
        const float a = 1.0f - s;
        const float lga = f_lg2(a);
        float a2 = a * a;
        const float D = a2 * a2;                  // a^4 exact
        const float rcs = f_rcp(s);

        const uint32_t bb = sthr + (uint32_t)bufsel * (4u * TT);
        float* scr = smem + OFF_SCR + scrsel * SCR_SIZE;

        // ---- 2. pass 1 data loads FIRST (critical path, LSU clean) ----
        float4 vv[4];
        #pragma unroll
        for (int c = 0; c < 4; c++)
            vv[c] = active ? lds128(bb + (uint32_t)c * (4u * CHUNK))
                           : make_float4(0.f, 0.f, 0.f, 0.f);

        // ---- 3. NOW issue nrow's prefetch into the free buffer ----
        if (nrow < rows && active) {
            const long long no = (long long)nrow * TT;
            const uint32_t nb = sthr + (uint32_t)(bufsel ^ 1) * (4u * TT);
            #pragma unroll
            for (int c = 0; c < 4; c++)
                cp16(nb + (uint32_t)c * (4u * CHUNK), x + no + c * CHUNK + 4 * t);
        }
        asm volatile("cp.async.commit_group;");

        // ---- pass 1: local Horner per chunk ----
        float Fv[4];
        #pragma unroll
        for (int c = 0; c < 4; c++) {
            float4 v = vv[c];
            float w0 = (t == 0 && c == 0) ? v.x * rcs : v.x;   // fold n[-1]=x0/s
            float Fvc = w0;
            Fvc = fmaf(a, Fvc, v.y);
            Fvc = fmaf(a, Fvc, v.z);
            Fvc = fmaf(a, Fvc, v.w);
            Fv[c] = Fvc;
        }

        // ---- level 2: fused warp scan (4 chains) ----
        float pw = D;
        #pragma unroll
        for (int off = 1; off < 32; off <<= 1) {
            float u0 = __shfl_up_sync(0xFFFFFFFFu, Fv[0], off);
            float u1 = __shfl_up_sync(0xFFFFFFFFu, Fv[1], off);
            float u2 = __shfl_up_sync(0xFFFFFFFFu, Fv[2], off);
            float u3 = __shfl_up_sync(0xFFFFFFFFu, Fv[3], off);
            if (lane >= off) {
                Fv[0] = fmaf(pw, u0, Fv[0]);
                Fv[1] = fmaf(pw, u1, Fv[1]);
                Fv[2] = fmaf(pw, u2, Fv[2]);
                Fv[3] = fmaf(pw, u3, Fv[3]);
            }
            pw *= pw;
        }
        const float Dw = pw;                      // a^128
        const float pl = f_ex2((float)lane * (4.0f * lga));   // D^lane

        if (lane == 31) {
            #pragma unroll
            for (int c = 0; c < 4; c++) scr[c * 16 + wid] = Fv[c];
        }
        if (t == 499) {
            #pragma unroll
            for (int c = 0; c < 4; c++) scr[64 + c] = Fv[c];
        }

        // ---- grab row-after-next (pre-barrier publish) ----
        if (t == 0) {
            int n2 = atomicAdd(&g_next_row, 1);
            scr[68] = __int_as_float(n2);
        }

        float vex[4];
        #pragma unroll
        for (int c = 0; c < 4; c++) {
            vex[c] = __shfl_up_sync(0xFFFFFFFFu, Fv[c], 1);
            if (lane == 0) vex[c] = 0.0f;
        }

        __syncthreads();                          // the ONLY barrier per row

        // ---- read row-after-next id + its s ----
        const int n2row = __float_as_int(scr[68]);
        float s_n2 = 0.0f;
        if (n2row < rows) {
            int nf = (Fmask >= 0) ? (n2row & Fmask) : (n2row % F);
            s_n2 = __ldg(log_s + nf);
        }

        // ---- level 3: 16-wide scan of warp totals (all warps redundant) ----
        float w[4];
        {
            const int ln = lane & 15;
            #pragma unroll
            for (int c = 0; c < 4; c++) w[c] = scr[c * 16 + ln];
        }
        float q = Dw;
        #pragma unroll
        for (int off = 1; off < 16; off <<= 1) {
            float u0 = __shfl_up_sync(0xFFFFFFFFu, w[0], off);
            float u1 = __shfl_up_sync(0xFFFFFFFFu, w[1], off);
            float u2 = __shfl_up_sync(0xFFFFFFFFu, w[2], off);
            float u3 = __shfl_up_sync(0xFFFFFFFFu, w[3], off);
            if (lane >= off) {
                w[0] = fmaf(q, u0, w[0]);
                w[1] = fmaf(q, u1, w[1]);
                w[2] = fmaf(q, u2, w[2]);
                w[3] = fmaf(q, u3, w[3]);
            }
            q *= q;
        }

        // chunk totals: T_c = a^80 * (state through warp 14) + thread499 partial
        const float a80 = f_ex2(80.0f * lga);
        float T0, T1, T2;
        {
            float e0 = __shfl_sync(0xFFFFFFFFu, w[0], 14);
            float e1 = __shfl_sync(0xFFFFFFFFu, w[1], 14);
            float e2 = __shfl_sync(0xFFFFFFFFu, w[2], 14);
            T0 = fmaf(a80, e0, scr[64]);
            T1 = fmaf(a80, e1, scr[65]);
            T2 = fmaf(a80, e2, scr[66]);
        }
        const float az = f_ex2(2000.0f * lga);
        const float S1 = T0;
        const float S2 = fmaf(az, S1, T1);
        const float S3 = fmaf(az, S2, T2);

        const int src = (wid == 0) ? 0 : (wid - 1);
        float ex[4];
        #pragma unroll
        for (int c = 0; c < 4; c++) {
            ex[c] = __shfl_sync(0xFFFFFFFFu, w[c], src);
            if (wid == 0) ex[c] = 0.0f;
        }
        const float plw = f_ex2((float)wid * (128.0f * lga));  // Dw^wid

        float carry[4];
        carry[0] = fmaf(pl, ex[0], vex[0]);
        carry[1] = fmaf(pl, fmaf(plw, S1, ex[1]), vex[1]);
        carry[2] = fmaf(pl, fmaf(plw, S2, ex[2]), vex[2]);
        carry[3] = fmaf(pl, fmaf(plw, S3, ex[3]), vex[3]);

        // ---- pass 2: re-read buffer, replay + epilogue, .cs stores ----
        if (active) {
            float* orow = out + (long long)row * TT;
            #pragma unroll
            for (int c = 0; c < 4; c++) {
                float4 v = lds128(bb + (uint32_t)c * (4u * CHUNK));
                float w0 = (t == 0 && c == 0) ? v.x * rcs : v.x;
                float n = carry[c];
                float o0, o1, o2, o3;
                n = fmaf(a, n, w0);
                { float l = f_lg2(fmaf(s, n, EPS_C));
                  float p = f_ex2(-ALPHA_C * l);
                  o0 = f_sqrt(fmaf(v.x, p, DELTA_C)) - SQRT_DELTA; }
                n = fmaf(a, n, v.y);
                { float l = f_lg2(fmaf(s, n, EPS_C));
                  float p = f_ex2(-ALPHA_C * l);
                  o1 = f_sqrt(fmaf(v.y, p, DELTA_C)) - SQRT_DELTA; }
                n = fmaf(a, n, v.z);
                { float l = f_lg2(fmaf(s, n, EPS_C));
                  float p = f_ex2(-ALPHA_C * l);
                  o2 = f_sqrt(fmaf(v.z, p, DELTA_C)) - SQRT_DELTA; }
                n = fmaf(a, n, v.w);
                { float l = f_lg2(fmaf(s, n, EPS_C));
                  float p = f_ex2(-ALPHA_C * l);
                  o3 = f_sqrt(fmaf(v.w, p, DELTA_C)) - SQRT_DELTA; }
                stg_cs(orow + c * CHUNK + 4 * t, o0, o1, o2, o3);
            }
        }

        // ---- rotate ----
        row = nrow; s_cur = s_nx;
        nrow = n2row; s_nx = s_n2;
        bufsel ^= 1; scrsel ^= 1;
    }
}

extern "C" void kernel_launch(void* const* d_in, const int* in_sizes, int n_in,
                              void* d_out, int out_size)
{
    int xi = 0, si = 1;
    if (n_in >= 2 && in_sizes[0] < in_sizes[1]) { xi = 1; si = 0; }

    const float* x     = (const float*)d_in[xi];
    const float* log_s = (const float*)d_in[si];
    float*       out   = (float*)d_out;

    const int F    = in_sizes[si];           // 128
    const int rows = in_sizes[xi] / TT;      // B*F = 4096
    const int Fmask = ((F & (F - 1)) == 0) ? (F - 1) : -1;

    const int smem_bytes = SMEM_FLOATS * (int)sizeof(float);   // ~64.6 KB
    cudaFuncSetAttribute(pcen_kernel,
                         cudaFuncAttributeMaxDynamicSharedMemorySize, smem_bytes);

    pcen_init<<<1, 1>>>();
    int grid = GRID_MAX; if (grid > rows) grid = rows;
    pcen_kernel<<<grid, NTH, smem_bytes>>>(x, log_s, out, F, Fmask, rows);
}

// round 17
// speedup vs baseline: 1.0322x; 1.0322x over previous
#include <cuda_runtime.h>
#include <cuda_bf16.h>
#include <cstdint>

// PCEN via exact parallel linear-recurrence scan (constant per-row decay a=1-s).
// R17: FULL-occupancy redesign. Single 32KB smem row buffer; pass1 = direct
// coalesced LDG.128 burst -> regs -> Horner + STS (thread-private slots, no
// extra barriers); pass2 re-reads from smem. smem 32.6KB -> 4 CTAs/SM = 2048
// threads (100% occ), launch_bounds(512,4) caps regs at 32. Dynamic row
// mailbox as in R14 (best previous). 16 warps/SMSP hide the per-row LDG burst.

#define TT     8000
#define CHUNK  2000
#define NTH    512
#define GRID_MAX 592            // 4 CTAs/SM * 148 SMs
#define ALPHA_C 0.98f
#define DELTA_C 2.0f
#define EPS_C   1e-6f
#define SQRT_DELTA 1.41421356237f
#define LOG2E 1.44269504089f

// smem floats: buf[8000], scr[2][72]
// scr layout: [0..63] warp totals, [64..67] t499 partials, [68] mailbox
#define OFF_SCR   (TT)
#define SCR_SIZE  72
#define SMEM_FLOATS (TT + 2*SCR_SIZE)

__device__ int g_next_row;

__global__ void pcen_init() { g_next_row = 0; }

__device__ __forceinline__ float f_lg2(float x) {
    float r; asm("lg2.approx.f32 %0, %1;" : "=f"(r) : "f"(x)); return r;
}
__device__ __forceinline__ float f_ex2(float x) {
    float r; asm("ex2.approx.f32 %0, %1;" : "=f"(r) : "f"(x)); return r;
}
__device__ __forceinline__ float f_sqrt(float x) {
    float r; asm("sqrt.approx.f32 %0, %1;" : "=f"(r) : "f"(x)); return r;
}
__device__ __forceinline__ float f_rcp(float x) {
    float r; asm("rcp.approx.f32 %0, %1;" : "=f"(r) : "f"(x)); return r;
}
__device__ __forceinline__ void stg_cs(float* g, float a, float b, float c, float d) {
    asm volatile("st.global.cs.v4.f32 [%0], {%1,%2,%3,%4};"
                 :: "l"(g), "f"(a), "f"(b), "f"(c), "f"(d));
}
__device__ __forceinline__ float4 lds128(uint32_t saddr) {
    float4 v;
    asm volatile("ld.shared.v4.f32 {%0,%1,%2,%3}, [%4];"
                 : "=f"(v.x), "=f"(v.y), "=f"(v.z), "=f"(v.w) : "r"(saddr));
    return v;
}
__device__ __forceinline__ void sts128(uint32_t saddr, float4 v) {
    asm volatile("st.shared.v4.f32 [%0], {%1,%2,%3,%4};"
                 :: "r"(saddr), "f"(v.x), "f"(v.y), "f"(v.z), "f"(v.w));
}

__global__ __launch_bounds__(NTH, 4)
void pcen_kernel(const float* __restrict__ x,
                 const float* __restrict__ log_s,
                 float* __restrict__ out,
                 int F, int Fmask, int rows)
{
    extern __shared__ float smem[];

    const int t    = threadIdx.x;
    const bool active = (t < CHUNK / 4);       // threads 0..499
    const int lane = t & 31;
    const int wid  = t >> 5;                   // 0..15

    const uint32_t sbase = (uint32_t)__cvta_generic_to_shared(smem);
    const uint32_t sthr  = sbase + 16u * (uint32_t)t;   // slot in chunk 0

    // ---- prologue: grab first row ----
    if (t == 0) {
        int r0 = atomicAdd(&g_next_row, 1);
        smem[OFF_SCR + 68] = __int_as_float(r0);
    }
    __syncthreads();
    int row = __float_as_int(smem[OFF_SCR + 68]);
    __syncthreads();   // all reads done before later scr writes

    float s_cur = 0.0f;
    if (row < rows) {
        int f0 = (Fmask >= 0) ? (row & Fmask) : (row % F);
        s_cur = __ldg(log_s + f0);
    }

    int scrsel = 0;
    while (row < rows) {
        // ---- pass 0: coalesced LDG.128 burst (4 chunks, MLP=4) ----
        float4 vv[4];
        if (active) {
            const float* xr = x + (long long)row * TT + 4 * t;
            #pragma unroll
            for (int c = 0; c < 4; c++)
                vv[c] = __ldg((const float4*)(xr + c * CHUNK));
        } else {
            #pragma unroll
            for (int c = 0; c < 4; c++) vv[c] = make_float4(0.f, 0.f, 0.f, 0.f);
        }

        // ---- per-row constants (overlap the LDG flight) ----
        const float s = f_ex2(LOG2E * s_cur);
        const float a = 1.0f - s;
        const float lga = f_lg2(a);
        float a2 = a * a;
        const float D = a2 * a2;                  // a^4 exact
        const float rcs = f_rcp(s);

        float* scr = smem + OFF_SCR + scrsel * SCR_SIZE;

        // ---- pass 1: STS to the (thread-private) buffer + local Horner ----
        float Fv[4];
        #pragma unroll
        for (int c = 0; c < 4; c++) {
            float4 v = vv[c];
            if (active) sts128(sthr + (uint32_t)c * (4u * CHUNK), v);
            float w0 = (t == 0 && c == 0) ? v.x * rcs : v.x;   // fold n[-1]=x0/s
            float Fvc = w0;
            Fvc = fmaf(a, Fvc, v.y);
            Fvc = fmaf(a, Fvc, v.z);
            Fvc = fmaf(a, Fvc, v.w);
            Fv[c] = Fvc;
        }

        // ---- level 2: fused warp scan (4 chains) ----
        float pw = D;
        #pragma unroll
        for (int off = 1; off < 32; off <<= 1) {
            float u0 = __shfl_up_sync(0xFFFFFFFFu, Fv[0], off);
            float u1 = __shfl_up_sync(0xFFFFFFFFu, Fv[1], off);
            float u2 = __shfl_up_sync(0xFFFFFFFFu, Fv[2], off);
            float u3 = __shfl_up_sync(0xFFFFFFFFu, Fv[3], off);
            if (lane >= off) {
                Fv[0] = fmaf(pw, u0, Fv[0]);
                Fv[1] = fmaf(pw, u1, Fv[1]);
                Fv[2] = fmaf(pw, u2, Fv[2]);
                Fv[3] = fmaf(pw, u3, Fv[3]);
            }
            pw *= pw;
        }
        const float Dw = pw;                      // a^128
        const float pl = f_ex2((float)lane * (4.0f * lga));   // D^lane

        if (lane == 31) {
            #pragma unroll
            for (int c = 0; c < 4; c++) scr[c * 16 + wid] = Fv[c];
        }
        if (t == 499) {
            #pragma unroll
            for (int c = 0; c < 4; c++) scr[64 + c] = Fv[c];
        }

        // ---- grab next row (pre-barrier publish) ----
        if (t == 0) {
            int nr = atomicAdd(&g_next_row, 1);
            scr[68] = __int_as_float(nr);
        }

        float vex[4];
        #pragma unroll
        for (int c = 0; c < 4; c++) {
            vex[c] = __shfl_up_sync(0xFFFFFFFFu, Fv[c], 1);
            if (lane == 0) vex[c] = 0.0f;
        }

        __syncthreads();                          // the ONLY barrier per row

        // ---- read next row id + start its s load ----
        const int nrow = __float_as_int(scr[68]);
        float s_nx = 0.0f;
        if (nrow < rows) {
            int nf = (Fmask >= 0) ? (nrow & Fmask) : (nrow % F);
            s_nx = __ldg(log_s + nf);
        }

        // ---- level 3: 16-wide scan of warp totals (all warps redundant) ----
        float w[4];
        {
            const int ln = lane & 15;
            #pragma unroll
            for (int c = 0; c < 4; c++) w[c] = scr[c * 16 + ln];
        }
        float q = Dw;
        #pragma unroll
        for (int off = 1; off < 16; off <<= 1) {
            float u0 = __shfl_up_sync(0xFFFFFFFFu, w[0], off);
            float u1 = __shfl_up_sync(0xFFFFFFFFu, w[1], off);
            float u2 = __shfl_up_sync(0xFFFFFFFFu, w[2], off);
            float u3 = __shfl_up_sync(0xFFFFFFFFu, w[3], off);
            if (lane >= off) {
                w[0] = fmaf(q, u0, w[0]);
                w[1] = fmaf(q, u1, w[1]);
                w[2] = fmaf(q, u2, w[2]);
                w[3] = fmaf(q, u3, w[3]);
            }
            q *= q;
        }

        // chunk totals: T_c = a^80 * (state through warp 14) + thread499 partial
        const float a80 = f_ex2(80.0f * lga);
        float T0, T1, T2;
        {
            float e0 = __shfl_sync(0xFFFFFFFFu, w[0], 14);
            float e1 = __shfl_sync(0xFFFFFFFFu, w[1], 14);
            float e2 = __shfl_sync(0xFFFFFFFFu, w[2], 14);
            T0 = fmaf(a80, e0, scr[64]);
            T1 = fmaf(a80, e1, scr[65]);
            T2 = fmaf(a80, e2, scr[66]);
        }
        const float az = f_ex2(2000.0f * lga);
        const float S1 = T0;
        const float S2 = fmaf(az, S1, T1);
        const float S3 = fmaf(az, S2, T2);

        const int src = (wid == 0) ? 0 : (wid - 1);
        float ex[4];
        #pragma unroll
        for (int c = 0; c < 4; c++) {
            ex[c] = __shfl_sync(0xFFFFFFFFu, w[c], src);
            if (wid == 0) ex[c] = 0.0f;
        }
        const float plw = f_ex2((float)wid * (128.0f * lga));  // Dw^wid

        float carry[4];
        carry[0] = fmaf(pl, ex[0], vex[0]);
        carry[1] = fmaf(pl, fmaf(plw, S1, ex[1]), vex[1]);
        carry[2] = fmaf(pl, fmaf(plw, S2, ex[2]), vex[2]);
        carry[3] = fmaf(pl, fmaf(plw, S3, ex[3]), vex[3]);

        // ---- pass 2: re-read own slots, replay + epilogue, .cs stores ----
        if (active) {
            float* orow = out + (long long)row * TT + 4 * t;
            #pragma unroll
            for (int c = 0; c < 4; c++) {
                float4 v = lds128(sthr + (uint32_t)c * (4u * CHUNK));
                float w0 = (t == 0 && c == 0) ? v.x * rcs : v.x;
                float n = carry[c];
                float o0, o1, o2, o3;
                n = fmaf(a, n, w0);
                { float l = f_lg2(fmaf(s, n, EPS_C));
                  float p = f_ex2(-ALPHA_C * l);
                  o0 = f_sqrt(fmaf(v.x, p, DELTA_C)) - SQRT_DELTA; }
                n = fmaf(a, n, v.y);
                { float l = f_lg2(fmaf(s, n, EPS_C));
                  float p = f_ex2(-ALPHA_C * l);
                  o1 = f_sqrt(fmaf(v.y, p, DELTA_C)) - SQRT_DELTA; }
                n = fmaf(a, n, v.z);
                { float l = f_lg2(fmaf(s, n, EPS_C));
                  float p = f_ex2(-ALPHA_C * l);
                  o2 = f_sqrt(fmaf(v.z, p, DELTA_C)) - SQRT_DELTA; }
                n = fmaf(a, n, v.w);
                { float l = f_lg2(fmaf(s, n, EPS_C));
                  float p = f_ex2(-ALPHA_C * l);
                  o3 = f_sqrt(fmaf(v.w, p, DELTA_C)) - SQRT_DELTA; }
                stg_cs(orow + c * CHUNK, o0, o1, o2, o3);
            }
        }

        // ---- rotate ----
        row = nrow; s_cur = s_nx;
        scrsel ^= 1;
    }
}

extern "C" void kernel_launch(void* const* d_in, const int* in_sizes, int n_in,
                              void* d_out, int out_size)
{
    int xi = 0, si = 1;
    if (n_in >= 2 && in_sizes[0] < in_sizes[1]) { xi = 1; si = 0; }

    const float* x     = (const float*)d_in[xi];
    const float* log_s = (const float*)d_in[si];
    float*       out   = (float*)d_out;

    const int F    = in_sizes[si];           // 128
    const int rows = in_sizes[xi] / TT;      // B*F = 4096
    const int Fmask = ((F & (F - 1)) == 0) ? (F - 1) : -1;

    const int smem_bytes = SMEM_FLOATS * (int)sizeof(float);   // ~32.6 KB
    cudaFuncSetAttribute(pcen_kernel,
                         cudaFuncAttributeMaxDynamicSharedMemorySize, smem_bytes);

    pcen_init<<<1, 1>>>();
    int grid = GRID_MAX; if (grid > rows) grid = rows;
    pcen_kernel<<<grid, NTH, smem_bytes>>>(x, log_s, out, F, Fmask, rows);
}